// round 15
// baseline (speedup 1.0000x reference)
#include <cuda_runtime.h>

// Problem constants (fixed by the reference)
#define NN        10000
#define CH        16
#define BATCH     8
#define E_EDGES   320000           // = 512 * 625
#define WSTRIDE   5120000          // floats between weight[i] planes
#define OUTPLANE  160000
#define NRES      625              // residue classes: n mod 625
#define FLATS     512              // (d,c) pairs per node
#define DEPTH     4
#define XSLOTF    1024             // x slot: 32 rows * 32 floats (4 KB)
#define WSLOTF    256              // w slot per warp: 2n*4i*32 (1 KB)
#define NODE_OFF  (NRES * 8)

// Scratch (allocation-free: __device__ global)
__device__ float g_xT[(NN + 1) * 32];   // [node][b*4+i], row NN = zeros

#define CP_A16(dst, src) \
    asm volatile("cp.async.cg.shared.global [%0], [%1], 16;" :: "r"(dst), "l"(src))
#define CP_COMMIT() asm volatile("cp.async.commit_group;")
#define CP_WAIT2()  asm volatile("cp.async.wait_group 2;")

// ---------------------------------------------------------------------------
// Prep: transpose only. One thread per (node, batch): 1 LDG.128 + 1 STG.128,
// depth-1 chain, fully coalesced both sides. 313 * 256 threads, single pass.
// ---------------------------------------------------------------------------
__global__ void prep_kernel(const float* __restrict__ x) {
    const int gt = blockIdx.x * blockDim.x + threadIdx.x;
    const int j  = gt >> 3;            // node (j == NN -> zero pad row)
    const int b  = gt & 7;             // batch
    if (j <= NN) {
        float4 v = make_float4(0.f, 0.f, 0.f, 0.f);
        if (j < NN)
            v = *(const float4*)(x + (size_t)b * (NN * 4) + (size_t)j * 4);
        *(float4*)(g_xT + (size_t)j * 32 + b * 4) = v;
    }
}

// ---------------------------------------------------------------------------
// Main: block (256 thr, 8 warps) = residue class r; warp w computes
// nA = r + 625*w, nB = r + 625*(w+8).
// Stage s covers flats 32s..32s+31 (d = 2s+dpar, lane = 16*dpar + c).
//  - edges read DIRECTLY (int64 or int32; per-block detection) into se[].
//  - x ring: 4 slots block-shared (gather via cp.async from g_xT, swizzled).
//  - w rings: 4-deep per-warp private.
//  - per stage: wait_group(2) + one __syncthreads, FILLS ISSUED BEFORE the
//    compute burst (copies start ~400cyc earlier; slot-reuse proof unchanged:
//    the stage-s barrier orders all stage s-1 reads before the refill).
// smem 51 KB, <=64 regs -> 4 blocks (32 warps)/SM.
// ---------------------------------------------------------------------------
__global__ __launch_bounds__(256, 4)
void lcg_main(const void* __restrict__ edges,
              const float* __restrict__ W, float* __restrict__ out) {
    __shared__ __align__(16) float xr[DEPTH][XSLOTF];    // 16384 B
    __shared__ __align__(16) float wr[8][DEPTH][WSLOTF]; // 32768 B
    __shared__ int se[FLATS];                            // 2048 B
    __shared__ int s_is32;
    const int r    = blockIdx.x;
    const int tid  = threadIdx.x;
    const int w    = tid >> 5;
    const int lane = tid & 31;

    // ---- dtype detection: int64 layout -> odd int32 words are zero
    //      high-words (values <= 10000). Samples in-bounds for BOTH layouts.
    if (tid == 0) s_is32 = 0;
    __syncthreads();
    if (tid < 64) {
        int slot = 2 * (tid * 2499) + 1;      // max 314875 < 320000
        if (((const int*)edges)[slot] != 0) atomicOr(&s_is32, 1);
    }
    __syncthreads();
    if (s_is32) {
        const int2* e = (const int2*)edges + r * (FLATS / 2) + tid;
        int2 v = *e;
        se[2 * tid] = v.x;  se[2 * tid + 1] = v.y;
    } else {
        const longlong2* e = (const longlong2*)edges + r * (FLATS / 2) + tid;
        longlong2 v = *e;
        se[2 * tid] = (int)v.x;  se[2 * tid + 1] = (int)v.y;
    }
    __syncthreads();

    // ---- x-ring fill geometry: row jx = tid>>3, chunk gx = tid&7
    const int jx = tid >> 3;
    const int gx = tid & 7;
    const unsigned xrb = (unsigned)__cvta_generic_to_shared(&xr[0][0]);
    const unsigned xd  = (unsigned)((jx * 32 + 4 * (gx ^ (jx & 7))) * 4);

    // ---- w-ring fill geometry: this warp's two nodes, plane ii, chunk gg
    const int ii = lane >> 3, gg = lane & 7;
    const float* wsrcA = W + (size_t)ii * WSTRIDE
                           + (size_t)(r + NRES * w) * FLATS + 4 * gg;
    const float* wsrcB = wsrcA + (size_t)NODE_OFF * FLATS;
    const unsigned wrb = (unsigned)__cvta_generic_to_shared(&wr[w][0][0]);
    const unsigned wdA = (unsigned)((ii * 32 + 4 * gg) * 4);
    const unsigned wdB = wdA + 128 * 4;

#define XFILL(n) do {                                                      \
        int e0 = se[32 * (n) + jx];                                        \
        CP_A16(xrb + (unsigned)(((n) & 3) * XSLOTF * 4) + xd,              \
               g_xT + (size_t)e0 * 32 + 4 * gx);                           \
    } while (0)

#define WFILL(n) do {                                                      \
        const unsigned ws = (unsigned)(((n) & 3) * WSLOTF * 4);            \
        CP_A16(wrb + ws + wdA, wsrcA + 32 * (n));                          \
        CP_A16(wrb + ws + wdB, wsrcB + 32 * (n));                          \
    } while (0)

    // ---- prologue: stages 0..2 in flight
#pragma unroll
    for (int p = 0; p < DEPTH - 1; ++p) {
        XFILL(p);
        WFILL(p);
        CP_COMMIT();
    }

    // ---- main loop
    float accA[BATCH], accB[BATCH];
#pragma unroll
    for (int b = 0; b < BATCH; ++b) { accA[b] = 0.0f; accB[b] = 0.0f; }

    const int swz = lane & 7;

#pragma unroll
    for (int s = 0; s < 16; ++s) {
        CP_WAIT2();            // groups through stage s landed
        __syncthreads();       // all x chunks visible; stage s-1 reads done

        // fills FIRST: refill slot (s-1)&3 (drained, per the barrier above)
        const int nx = s + DEPTH - 1;
        if (nx < 16) {
            XFILL(nx);
            WFILL(nx);
        }
        CP_COMMIT();           // exactly one commit per stage

        const int slot = s & 3;
        const float* wp = &wr[w][slot][lane];
        const float a0 = wp[0],   a1 = wp[32],  a2 = wp[64],  a3 = wp[96];
        const float b0 = wp[128], b1 = wp[160], b2 = wp[192], b3 = wp[224];

        const float4* __restrict__ rp =
            reinterpret_cast<const float4*>(&xr[slot][lane * 32]);
#pragma unroll
        for (int b = 0; b < BATCH; ++b) {
            float4 v = rp[b ^ swz];        // logical batch b (swizzled)
            accA[b] += v.x * a0 + v.y * a1 + v.z * a2 + v.w * a3;
            accB[b] += v.x * b0 + v.y * b1 + v.z * b2 + v.w * b3;
        }
    }

    // ---- combine d-parities (lane <-> lane^16), write out
#pragma unroll
    for (int b = 0; b < BATCH; ++b) {
        accA[b] += __shfl_xor_sync(0xffffffffu, accA[b], 16);
        accB[b] += __shfl_xor_sync(0xffffffffu, accB[b], 16);
    }

    const int nA = r + NRES * w;
    const int nB = nA + NODE_OFF;
    const int c    = lane & 15;
    const int half = lane >> 4;            // 0 -> batches 0..3, 1 -> 4..7
#pragma unroll
    for (int k = 0; k < 4; ++k) {
        const int b = half * 4 + k;
        out[b * OUTPLANE + nA * CH + c] = half ? accA[k + 4] : accA[k];
        out[b * OUTPLANE + nB * CH + c] = half ? accB[k + 4] : accB[k];
    }
#undef XFILL
#undef WFILL
}

// ---------------------------------------------------------------------------
// Launch
// ---------------------------------------------------------------------------
extern "C" void kernel_launch(void* const* d_in, const int* in_sizes, int n_in,
                              void* d_out, int out_size) {
    const float* x     = (const float*)d_in[0];   // (8,10000,4) f32
    const void*  edges = d_in[1];                 // (320000,) int64/int32
    const float* W     = (const float*)d_in[2];   // (4,320000,16) f32
    float*       out   = (float*)d_out;           // (8,10000,16) f32
    (void)in_sizes; (void)n_in; (void)out_size;

    prep_kernel<<<313, 256>>>(x);
    lcg_main<<<NRES, 256>>>(edges, W, out);
}

// round 16
// speedup vs baseline: 1.0083x; 1.0083x over previous
#include <cuda_runtime.h>

// Problem constants (fixed by the reference)
#define NN        10000
#define CH        16
#define BATCH     8
#define E_EDGES   320000           // = 512 * 625
#define WSTRIDE   5120000          // floats between weight[i] planes
#define OUTPLANE  160000
#define NRES      625              // residue classes: n mod 625
#define FLATS     512              // (d,c) pairs per node
#define DEPTH     4
#define XSLOTF    1024             // x slot: 32 rows * 32 floats (4 KB)
#define WSLOTF    256              // w slot per warp: 2n*4i*32 (1 KB)
#define NODE_OFF  (NRES * 8)

// Scratch (allocation-free: __device__ global)
__device__ float g_xT[(NN + 1) * 32];   // [node][b*4+i], row NN = zeros

#define CP_A16(dst, src) \
    asm volatile("cp.async.cg.shared.global [%0], [%1], 16;" :: "r"(dst), "l"(src))
#define CP_COMMIT() asm volatile("cp.async.commit_group;")
#define CP_WAIT2()  asm volatile("cp.async.wait_group 2;")

// ---------------------------------------------------------------------------
// Prep: transpose only. One thread per (node, batch): 1 LDG.128 + 1 STG.128,
// depth-1 chain, fully coalesced both sides.
// ---------------------------------------------------------------------------
__global__ void prep_kernel(const float* __restrict__ x) {
    const int gt = blockIdx.x * blockDim.x + threadIdx.x;
    const int j  = gt >> 3;            // node (j == NN -> zero pad row)
    const int b  = gt & 7;             // batch
    if (j <= NN) {
        float4 v = make_float4(0.f, 0.f, 0.f, 0.f);
        if (j < NN)
            v = *(const float4*)(x + (size_t)b * (NN * 4) + (size_t)j * 4);
        *(float4*)(g_xT + (size_t)j * 32 + b * 4) = v;
    }
}

// ---------------------------------------------------------------------------
// Main (R13 loop ordering: compute burst, THEN fills — best measured).
// Block (256 thr, 8 warps) = residue class r; warp w computes
// nA = r + 625*w, nB = r + 625*(w+8).
// Stage s covers flats 32s..32s+31 (d = 2s+dpar, lane = 16*dpar + c).
//  - edges read DIRECTLY (int64 or int32; per-block detection) into se[].
//  - x ring: 4 slots block-shared (cp.async gather from g_xT, swizzled).
//  - w rings: 4-deep per-warp private.
// smem 51 KB, 64 regs -> 4 blocks (32 warps)/SM (RF-capped).
// ---------------------------------------------------------------------------
__global__ __launch_bounds__(256, 4)
void lcg_main(const void* __restrict__ edges,
              const float* __restrict__ W, float* __restrict__ out) {
    __shared__ __align__(16) float xr[DEPTH][XSLOTF];    // 16384 B
    __shared__ __align__(16) float wr[8][DEPTH][WSLOTF]; // 32768 B
    __shared__ int se[FLATS];                            // 2048 B
    __shared__ int s_is32;
    const int r    = blockIdx.x;
    const int tid  = threadIdx.x;
    const int w    = tid >> 5;
    const int lane = tid & 31;

    // ---- dtype detection: int64 layout -> odd int32 words are zero
    //      high-words (values <= 10000). Samples in-bounds for BOTH layouts.
    if (tid == 0) s_is32 = 0;
    __syncthreads();
    if (tid < 64) {
        int slot = 2 * (tid * 2499) + 1;      // max 314875 < 320000
        if (((const int*)edges)[slot] != 0) atomicOr(&s_is32, 1);
    }
    __syncthreads();
    if (s_is32) {
        const int2* e = (const int2*)edges + r * (FLATS / 2) + tid;
        int2 v = *e;
        se[2 * tid] = v.x;  se[2 * tid + 1] = v.y;
    } else {
        const longlong2* e = (const longlong2*)edges + r * (FLATS / 2) + tid;
        longlong2 v = *e;
        se[2 * tid] = (int)v.x;  se[2 * tid + 1] = (int)v.y;
    }
    __syncthreads();

    // ---- x-ring fill geometry: row jx = tid>>3, chunk gx = tid&7
    const int jx = tid >> 3;
    const int gx = tid & 7;
    const unsigned xrb = (unsigned)__cvta_generic_to_shared(&xr[0][0]);
    const unsigned xd  = (unsigned)((jx * 32 + 4 * (gx ^ (jx & 7))) * 4);

    // ---- w-ring fill geometry: this warp's two nodes, plane ii, chunk gg
    const int ii = lane >> 3, gg = lane & 7;
    const float* wsrcA = W + (size_t)ii * WSTRIDE
                           + (size_t)(r + NRES * w) * FLATS + 4 * gg;
    const float* wsrcB = wsrcA + (size_t)NODE_OFF * FLATS;
    const unsigned wrb = (unsigned)__cvta_generic_to_shared(&wr[w][0][0]);
    const unsigned wdA = (unsigned)((ii * 32 + 4 * gg) * 4);
    const unsigned wdB = wdA + 128 * 4;

#define XFILL(n) do {                                                      \
        int e0 = se[32 * (n) + jx];                                        \
        CP_A16(xrb + (unsigned)(((n) & 3) * XSLOTF * 4) + xd,              \
               g_xT + (size_t)e0 * 32 + 4 * gx);                           \
    } while (0)

#define WFILL(n) do {                                                      \
        const unsigned ws = (unsigned)(((n) & 3) * WSLOTF * 4);            \
        CP_A16(wrb + ws + wdA, wsrcA + 32 * (n));                          \
        CP_A16(wrb + ws + wdB, wsrcB + 32 * (n));                          \
    } while (0)

    // ---- prologue: stages 0..2 in flight
#pragma unroll
    for (int p = 0; p < DEPTH - 1; ++p) {
        XFILL(p);
        WFILL(p);
        CP_COMMIT();
    }

    // ---- main loop
    float accA[BATCH], accB[BATCH];
#pragma unroll
    for (int b = 0; b < BATCH; ++b) { accA[b] = 0.0f; accB[b] = 0.0f; }

    const int swz = lane & 7;

#pragma unroll
    for (int s = 0; s < 16; ++s) {
        CP_WAIT2();            // groups through stage s landed
        __syncthreads();       // all x chunks visible; stage s-1 reads done

        const int slot = s & 3;

        const float* wp = &wr[w][slot][lane];
        const float a0 = wp[0],   a1 = wp[32],  a2 = wp[64],  a3 = wp[96];
        const float b0 = wp[128], b1 = wp[160], b2 = wp[192], b3 = wp[224];

        const float4* __restrict__ rp =
            reinterpret_cast<const float4*>(&xr[slot][lane * 32]);
#pragma unroll
        for (int b = 0; b < BATCH; ++b) {
            float4 v = rp[b ^ swz];        // logical batch b (swizzled)
            accA[b] += v.x * a0 + v.y * a1 + v.z * a2 + v.w * a3;
            accB[b] += v.x * b0 + v.y * b1 + v.z * b2 + v.w * b3;
        }

        // refill slot (s-1)&3: barrier above proves all reads of it finished
        const int nx = s + DEPTH - 1;
        if (nx < 16) {
            XFILL(nx);
            WFILL(nx);
        }
        CP_COMMIT();           // exactly one commit per stage
    }

    // ---- combine d-parities (lane <-> lane^16), write out
#pragma unroll
    for (int b = 0; b < BATCH; ++b) {
        accA[b] += __shfl_xor_sync(0xffffffffu, accA[b], 16);
        accB[b] += __shfl_xor_sync(0xffffffffu, accB[b], 16);
    }

    const int nA = r + NRES * w;
    const int nB = nA + NODE_OFF;
    const int c    = lane & 15;
    const int half = lane >> 4;            // 0 -> batches 0..3, 1 -> 4..7
#pragma unroll
    for (int k = 0; k < 4; ++k) {
        const int b = half * 4 + k;
        out[b * OUTPLANE + nA * CH + c] = half ? accA[k + 4] : accA[k];
        out[b * OUTPLANE + nB * CH + c] = half ? accB[k + 4] : accB[k];
    }
#undef XFILL
#undef WFILL
}

// ---------------------------------------------------------------------------
// Launch
// ---------------------------------------------------------------------------
extern "C" void kernel_launch(void* const* d_in, const int* in_sizes, int n_in,
                              void* d_out, int out_size) {
    const float* x     = (const float*)d_in[0];   // (8,10000,4) f32
    const void*  edges = d_in[1];                 // (320000,) int64/int32
    const float* W     = (const float*)d_in[2];   // (4,320000,16) f32
    float*       out   = (float*)d_out;           // (8,10000,16) f32
    (void)in_sizes; (void)n_in; (void)out_size;

    prep_kernel<<<313, 256>>>(x);
    lcg_main<<<NRES, 256>>>(edges, W, out);
}

// round 17
// speedup vs baseline: 1.0118x; 1.0036x over previous
#include <cuda_runtime.h>

// Problem constants (fixed by the reference)
#define NN        10000
#define CH        16
#define BATCH     8
#define E_EDGES   320000           // = 512 * 625
#define WSTRIDE   5120000          // floats between weight[i] planes
#define OUTPLANE  160000
#define NRES      625              // residue classes: n mod 625
#define FLATS     512              // (d,c) pairs per node
#define DEPTH     4
#define XSLOTF    1024             // x slot: 32 rows * 32 floats (4 KB)
#define WSLOTF    256              // w slot per warp: 2n*4i*32 (1 KB)
#define NODE_OFF  (NRES * 8)

// Scratch: g_xT row layout is now [node][i*8 + b]  (i-major, batch minor)
// so one 16B chunk = one plane i for 4 consecutive batches -> native f32x2 pairs.
__device__ float g_xT[(NN + 1) * 32];

#define CP_A16(dst, src) \
    asm volatile("cp.async.cg.shared.global [%0], [%1], 16;" :: "r"(dst), "l"(src))
#define CP_COMMIT() asm volatile("cp.async.commit_group;")
#define CP_WAIT2()  asm volatile("cp.async.wait_group 2;")

#define PACK2(d, s) \
    asm("mov.b64 %0, {%1, %2};" : "=l"(d) : "f"(s), "f"(s))
#define FMA2(acc, a, b) \
    asm("fma.rn.f32x2 %0, %1, %2, %0;" : "+l"(acc) : "l"(a), "l"(b))
#define LDS_V2U64(p0, p1, addr) \
    asm volatile("ld.shared.v2.u64 {%0, %1}, [%2];" \
                 : "=l"(p0), "=l"(p1) : "r"(addr))
#define UNPACK2(lo, hi, s) \
    asm("mov.b64 {%0, %1}, %2;" : "=f"(lo), "=f"(hi) : "l"(s))

// ---------------------------------------------------------------------------
// Prep: transpose into [i*8+b] rows. One thread per (node, batch):
// 1 coalesced LDG.128, 4 scalar stores (sector-dense). Row NN = zeros.
// ---------------------------------------------------------------------------
__global__ void prep_kernel(const float* __restrict__ x) {
    const int gt = blockIdx.x * blockDim.x + threadIdx.x;
    const int j  = gt >> 3;            // node
    const int b  = gt & 7;             // batch
    if (j <= NN) {
        float4 v = make_float4(0.f, 0.f, 0.f, 0.f);
        if (j < NN)
            v = *(const float4*)(x + (size_t)b * (NN * 4) + (size_t)j * 4);
        float* row = g_xT + (size_t)j * 32 + b;
        row[0] = v.x;  row[8] = v.y;  row[16] = v.z;  row[24] = v.w;
    }
}

// ---------------------------------------------------------------------------
// Main: block (256 thr, 8 warps) = residue class r; warp w computes
// nA = r + 625*w, nB = r + 625*(w+8). Stage counter s=0..15 maps to physical
// stage ps = (s + 4*((r>>2)&3)) & 15  (phase stagger decorrelates co-resident
// blocks; accumulation order is irrelevant).
// Compute uses packed f32x2 FMAs on (batch,batch+1) pairs read straight from
// the [i*8+b] row layout via ld.shared.v2.u64.
// smem 51 KB, <=64 regs -> 4 blocks (32 warps)/SM.
// ---------------------------------------------------------------------------
__global__ __launch_bounds__(256, 4)
void lcg_main(const void* __restrict__ edges,
              const float* __restrict__ W, float* __restrict__ out) {
    __shared__ __align__(16) float xr[DEPTH][XSLOTF];    // 16384 B
    __shared__ __align__(16) float wr[8][DEPTH][WSLOTF]; // 32768 B
    __shared__ int se[FLATS];                            // 2048 B
    __shared__ int s_is32;
    const int r    = blockIdx.x;
    const int tid  = threadIdx.x;
    const int w    = tid >> 5;
    const int lane = tid & 31;
    const int sphase = 4 * ((r >> 2) & 3);

    // ---- dtype detection (odd int32 words zero iff int64 layout)
    if (tid == 0) s_is32 = 0;
    __syncthreads();
    if (tid < 64) {
        int slot = 2 * (tid * 2499) + 1;      // in-bounds for both layouts
        if (((const int*)edges)[slot] != 0) atomicOr(&s_is32, 1);
    }
    __syncthreads();
    if (s_is32) {
        const int2* e = (const int2*)edges + r * (FLATS / 2) + tid;
        int2 v = *e;
        se[2 * tid] = v.x;  se[2 * tid + 1] = v.y;
    } else {
        const longlong2* e = (const longlong2*)edges + r * (FLATS / 2) + tid;
        longlong2 v = *e;
        se[2 * tid] = (int)v.x;  se[2 * tid + 1] = (int)v.y;
    }
    __syncthreads();

    // ---- x-ring fill geometry: row jx = tid>>3, chunk gx = tid&7
    const int jx = tid >> 3;
    const int gx = tid & 7;
    const unsigned xrb = (unsigned)__cvta_generic_to_shared(&xr[0][0]);
    const unsigned xd  = (unsigned)((jx * 32 + 4 * (gx ^ (jx & 7))) * 4);

    // ---- w-ring fill geometry
    const int ii = lane >> 3, gg = lane & 7;
    const float* wsrcA = W + (size_t)ii * WSTRIDE
                           + (size_t)(r + NRES * w) * FLATS + 4 * gg;
    const float* wsrcB = wsrcA + (size_t)NODE_OFF * FLATS;
    const unsigned wrb = (unsigned)__cvta_generic_to_shared(&wr[w][0][0]);
    const unsigned wdA = (unsigned)((ii * 32 + 4 * gg) * 4);
    const unsigned wdB = wdA + 128 * 4;

#define XFILL(n) do {                                                      \
        const int ps = ((n) + sphase) & 15;                                \
        int e0 = se[32 * ps + jx];                                         \
        CP_A16(xrb + (unsigned)(((n) & 3) * XSLOTF * 4) + xd,              \
               g_xT + (size_t)e0 * 32 + 4 * gx);                           \
    } while (0)

#define WFILL(n) do {                                                      \
        const int ps = ((n) + sphase) & 15;                                \
        const unsigned ws = (unsigned)(((n) & 3) * WSLOTF * 4);            \
        CP_A16(wrb + ws + wdA, wsrcA + 32 * ps);                           \
        CP_A16(wrb + ws + wdB, wsrcB + 32 * ps);                           \
    } while (0)

    // ---- prologue: counters 0..2 in flight
#pragma unroll
    for (int p = 0; p < DEPTH - 1; ++p) {
        XFILL(p);
        WFILL(p);
        CP_COMMIT();
    }

    // ---- main loop: packed accumulators (batch pairs)
    unsigned long long accA2[4] = {0ull, 0ull, 0ull, 0ull};
    unsigned long long accB2[4] = {0ull, 0ull, 0ull, 0ull};

    const int swz = lane & 7;
    const unsigned xlane = (unsigned)(lane * 128);   // lane's row offset bytes

#pragma unroll
    for (int s = 0; s < 16; ++s) {
        CP_WAIT2();            // groups through counter s landed
        __syncthreads();       // all x chunks visible; counter s-1 reads done

        const int slot = s & 3;
        const float* wp = &wr[w][slot][lane];
        const unsigned xbase = xrb + (unsigned)(slot * XSLOTF * 4) + xlane;

#pragma unroll
        for (int i = 0; i < 4; ++i) {
            unsigned long long wA2, wB2;
            PACK2(wA2, wp[32 * i]);
            PACK2(wB2, wp[128 + 32 * i]);
#pragma unroll
            for (int h = 0; h < 2; ++h) {
                const int m = 2 * i + h;               // logical chunk
                unsigned long long p0, p1;             // (b0,b1),(b2,b3) of group
                LDS_V2U64(p0, p1, xbase + (unsigned)(((m ^ swz) & 7) << 4));
                FMA2(accA2[2 * h + 0], p0, wA2);
                FMA2(accA2[2 * h + 1], p1, wA2);
                FMA2(accB2[2 * h + 0], p0, wB2);
                FMA2(accB2[2 * h + 1], p1, wB2);
            }
        }

        // refill slot (s-1)&3: barrier above proves all reads finished
        const int nx = s + DEPTH - 1;
        if (nx < 16) {
            XFILL(nx);
            WFILL(nx);
        }
        CP_COMMIT();           // exactly one commit per counter
    }

    // ---- unpack, combine d-parities (lane <-> lane^16), write out
    float accA[BATCH], accB[BATCH];
#pragma unroll
    for (int p = 0; p < 4; ++p) {
        UNPACK2(accA[2 * p], accA[2 * p + 1], accA2[p]);
        UNPACK2(accB[2 * p], accB[2 * p + 1], accB2[p]);
    }
#pragma unroll
    for (int b = 0; b < BATCH; ++b) {
        accA[b] += __shfl_xor_sync(0xffffffffu, accA[b], 16);
        accB[b] += __shfl_xor_sync(0xffffffffu, accB[b], 16);
    }

    const int nA = r + NRES * w;
    const int nB = nA + NODE_OFF;
    const int c    = lane & 15;
    const int half = lane >> 4;            // 0 -> batches 0..3, 1 -> 4..7
#pragma unroll
    for (int k = 0; k < 4; ++k) {
        const int b = half * 4 + k;
        out[b * OUTPLANE + nA * CH + c] = half ? accA[k + 4] : accA[k];
        out[b * OUTPLANE + nB * CH + c] = half ? accB[k + 4] : accB[k];
    }
#undef XFILL
#undef WFILL
}

// ---------------------------------------------------------------------------
// Launch
// ---------------------------------------------------------------------------
extern "C" void kernel_launch(void* const* d_in, const int* in_sizes, int n_in,
                              void* d_out, int out_size) {
    const float* x     = (const float*)d_in[0];   // (8,10000,4) f32
    const void*  edges = d_in[1];                 // (320000,) int64/int32
    const float* W     = (const float*)d_in[2];   // (4,320000,16) f32
    float*       out   = (float*)d_out;           // (8,10000,16) f32
    (void)in_sizes; (void)n_in; (void)out_size;

    prep_kernel<<<313, 256>>>(x);
    lcg_main<<<NRES, 256>>>(edges, W, out);
}